// round 14
// baseline (speedup 1.0000x reference)
#include <cuda_runtime.h>
#include <cuda_fp16.h>
#include <cstdint>

// Problem shape (fixed by the dataset)
#define M_DIM 4096
#define K_DIM 4096
#define N_DIM 11008
#define QW 2048   // qweight int32 words per output row (K/2)

// Scratch (no allocs allowed): f16 operands + row sums
__device__ __half g_xh[(size_t)M_DIM * K_DIM];   // 32 MB, exact integer q in [-127,127]
__device__ __half g_wh[(size_t)N_DIM * K_DIM];   // 90 MB, exact integer w in [0,15]
__device__ int g_rowsum[M_DIM];

// ---------------------------------------------------------------------------
// PTX helpers
// ---------------------------------------------------------------------------
__device__ __forceinline__ void cp16(uint32_t dst, const void* src) {
    asm volatile("cp.async.cg.shared.global [%0], [%1], 16;" :: "r"(dst), "l"(src));
}
#define CP_COMMIT() asm volatile("cp.async.commit_group;")
__device__ __forceinline__ void ldsm4(int& r0, int& r1, int& r2, int& r3, uint32_t addr) {
    asm volatile("ldmatrix.sync.aligned.m8n8.x4.shared.b16 {%0,%1,%2,%3}, [%4];"
                 : "=r"(r0), "=r"(r1), "=r"(r2), "=r"(r3) : "r"(addr));
}
__device__ __forceinline__ void mma_f16(float* d, const int* a, int b0, int b1) {
    asm volatile("mma.sync.aligned.m16n8k16.row.col.f32.f16.f16.f32 "
                 "{%0,%1,%2,%3}, {%4,%5,%6,%7}, {%8,%9}, {%0,%1,%2,%3};"
                 : "+f"(d[0]), "+f"(d[1]), "+f"(d[2]), "+f"(d[3])
                 : "r"(a[0]), "r"(a[1]), "r"(a[2]), "r"(a[3]), "r"(b0), "r"(b1));
}

// ---------------------------------------------------------------------------
// Kernel 1: static fake-quant of x -> exact f16 integers + per-row sums.
// ---------------------------------------------------------------------------
__global__ __launch_bounds__(256) void quantize_kernel(const float* __restrict__ x,
                                                       const float* __restrict__ clampv) {
    const int m = blockIdx.x;
    const float cv = clampv[0];
    const float a_scale = cv / 127.0f;
    const float* xrow = x + (size_t)m * K_DIM;
    const int t = threadIdx.x;

    int q[16];
#pragma unroll
    for (int i = 0; i < 4; i++) {
        float4 v = *reinterpret_cast<const float4*>(xrow + 16 * t + 4 * i);
        q[4 * i + 0] = __float2int_rn(fminf(fmaxf(v.x, -cv), cv) / a_scale);
        q[4 * i + 1] = __float2int_rn(fminf(fmaxf(v.y, -cv), cv) / a_scale);
        q[4 * i + 2] = __float2int_rn(fminf(fmaxf(v.z, -cv), cv) / a_scale);
        q[4 * i + 3] = __float2int_rn(fminf(fmaxf(v.w, -cv), cv) / a_scale);
    }
    int local_sum = 0;
#pragma unroll
    for (int i = 0; i < 16; i++) local_sum += q[i];

    __half2 h[8];
#pragma unroll
    for (int i = 0; i < 8; i++)
        h[i] = __halves2half2(__int2half_rn(q[2 * i]), __int2half_rn(q[2 * i + 1]));
    __half* dst = g_xh + (size_t)m * K_DIM + 16 * t;
    *reinterpret_cast<int4*>(dst)     = *reinterpret_cast<int4*>(&h[0]);
    *reinterpret_cast<int4*>(dst + 8) = *reinterpret_cast<int4*>(&h[4]);

    int s = local_sum;
#pragma unroll
    for (int off = 16; off > 0; off >>= 1) s += __shfl_down_sync(0xFFFFFFFFu, s, off);
    __shared__ int wsum[8];
    const int lane = threadIdx.x & 31, wid = threadIdx.x >> 5;
    if (lane == 0) wsum[wid] = s;
    __syncthreads();
    if (threadIdx.x == 0) {
        int tot = 0;
#pragma unroll
        for (int i = 0; i < 8; i++) tot += wsum[i];
        g_rowsum[m] = tot;
    }
}

// ---------------------------------------------------------------------------
// Kernel 2: unpack int4 nibbles -> exact f16 weights.
// ---------------------------------------------------------------------------
__global__ __launch_bounds__(256) void unpack_kernel(const int* __restrict__ qweight) {
    const int o = blockIdx.x;
    const int t = threadIdx.x;
    const int* qrow = qweight + (size_t)o * QW + 8 * t;
    int4 q0 = *reinterpret_cast<const int4*>(qrow);
    int4 q1 = *reinterpret_cast<const int4*>(qrow + 4);
    const int* ql = &q0.x;
    const int* qh = &q1.x;

    __half2 h[8];
#pragma unroll
    for (int c = 0; c < 4; c++) {
        h[c]     = __halves2half2(__int2half_rn((ql[c] >> 4) & 15), __int2half_rn(ql[c] & 15));
        h[4 + c] = __halves2half2(__int2half_rn((qh[c] >> 4) & 15), __int2half_rn(qh[c] & 15));
    }
    __half* dst = g_wh + (size_t)o * K_DIM + 16 * t;
    *reinterpret_cast<int4*>(dst)     = *reinterpret_cast<int4*>(&h[0]);
    *reinterpret_cast<int4*>(dst + 8) = *reinterpret_cast<int4*>(&h[4]);
}

// ---------------------------------------------------------------------------
// Kernel 3: pure-HMMA f16 GEMM, exact integer math.
// Block tile 256(M)x128(N), BK=64, 8 warps (4Mx2N), warp tile 64x64.
// 3-stage cp.async pipeline, XOR-swizzled 128B smem rows.
// Smem bytes/output cut 2.3x vs 128x128/32x64 config (crossbar relief).
// ---------------------------------------------------------------------------
#define BM 256
#define BN 128
#define BK 64
#define ROWB 128                    // bytes per smem row (= BK*2)
#define A_STG (BM * ROWB)           // 32 KB
#define STG (A_STG + BN * ROWB)     // 48 KB per stage
#define NCHUNK (K_DIM / BK)         // 64

__global__ __launch_bounds__(256, 1) void gemm_kernel(const int* __restrict__ qzeros,
                                                      const float* __restrict__ scales,
                                                      const float* __restrict__ bias,
                                                      const float* __restrict__ clampv,
                                                      float* __restrict__ out) {
    extern __shared__ __align__(128) char smem[];
    const uint32_t sb = (uint32_t)__cvta_generic_to_shared(smem);

    const int tid = threadIdx.x;
    const int wid = tid >> 5, lane = tid & 31;
    const int wm = wid & 3, wn = wid >> 2;           // 4 warps in M, 2 in N
    const int m0 = blockIdx.y * BM, n0 = blockIdx.x * BN;

    // ldmatrix per-lane addressing (validated mapping from R8)
    const int rin = lane & 15, seg = lane >> 4;
    int arow[4], akey[4];
#pragma unroll
    for (int mt = 0; mt < 4; mt++) {
        const int r = wm * 64 + mt * 16 + rin;
        arow[mt] = r * ROWB;
        akey[mt] = r & 7;
    }
    int brow[4], bkey[4];
#pragma unroll
    for (int oc = 0; oc < 4; oc++) {
        const int r = wn * 64 + oc * 16 + rin;
        brow[oc] = r * ROWB;
        bkey[oc] = r & 7;
    }

    // cp.async per-thread mapping: rows of 8x16B chunks
    const int ldc = tid & 7;     // 16B chunk within row
    const int ldr = tid >> 3;    // row 0..31 (+32*i)

    float acc[4][8][4];
#pragma unroll
    for (int mt = 0; mt < 4; mt++)
#pragma unroll
        for (int o = 0; o < 8; o++)
#pragma unroll
            for (int r = 0; r < 4; r++) acc[mt][o][r] = 0.0f;

    auto load_chunk = [&](int kt, int stage) {
        const uint32_t ab = sb + stage * STG;
        const uint32_t bb = ab + A_STG;
        const size_t koff = (size_t)kt * BK + ldc * 8;   // halves
#pragma unroll
        for (int i = 0; i < 8; i++) {                    // A: 256 rows
            const int r = ldr + 32 * i;
            const uint32_t sw = (uint32_t)(r * ROWB + ((ldc ^ (r & 7)) << 4));
            cp16(ab + sw, g_xh + (size_t)(m0 + r) * K_DIM + koff);
        }
#pragma unroll
        for (int i = 0; i < 4; i++) {                    // B: 128 rows
            const int r = ldr + 32 * i;
            const uint32_t sw = (uint32_t)(r * ROWB + ((ldc ^ (r & 7)) << 4));
            cp16(bb + sw, g_wh + (size_t)(n0 + r) * K_DIM + koff);
        }
        CP_COMMIT();
    };

    load_chunk(0, 0);
    load_chunk(1, 1);

#pragma unroll 1
    for (int kt = 0; kt < NCHUNK; kt++) {
        if (kt + 2 < NCHUNK) {
            load_chunk(kt + 2, (kt + 2) % 3);
            asm volatile("cp.async.wait_group 2;");
        } else if (kt + 1 < NCHUNK) {
            asm volatile("cp.async.wait_group 1;");
        } else {
            asm volatile("cp.async.wait_group 0;");
        }
        __syncthreads();

        const uint32_t ab = sb + (kt % 3) * STG;
        const uint32_t bb = ab + A_STG;
#pragma unroll
        for (int s = 0; s < 4; s++) {               // four k16 steps
            const int cidx = 2 * s + seg;
            int a[4][4], b[4][4];
#pragma unroll
            for (int mt = 0; mt < 4; mt++)
                ldsm4(a[mt][0], a[mt][1], a[mt][2], a[mt][3],
                      ab + (uint32_t)(arow[mt] + ((cidx ^ akey[mt]) << 4)));
#pragma unroll
            for (int oc = 0; oc < 4; oc++)
                ldsm4(b[oc][0], b[oc][1], b[oc][2], b[oc][3],
                      bb + (uint32_t)(brow[oc] + ((cidx ^ bkey[oc]) << 4)));
#pragma unroll
            for (int mt = 0; mt < 4; mt++)
#pragma unroll
                for (int oc = 0; oc < 4; oc++) {
                    mma_f16(acc[mt][oc * 2 + 0], a[mt], b[oc][0], b[oc][2]);
                    mma_f16(acc[mt][oc * 2 + 1], a[mt], b[oc][1], b[oc][3]);
                }
        }
        __syncthreads();
    }

    // ---- epilogue: out = sc*(acc - z*rowsum) + bias (all exact integers)
    const float cv = clampv[0];
    const float a_scale = cv / 127.0f;
    const int g = lane >> 2, tg = lane & 3;

    float scf[8][2], bif[8][2], zzf[8][2];
#pragma unroll
    for (int o = 0; o < 8; o++) {
        const int col = n0 + wn * 64 + (o >> 1) * 16 + (o & 1) * 8 + tg * 2;
#pragma unroll
        for (int j = 0; j < 2; j++) {
            scf[o][j] = scales[col + j] * a_scale;
            zzf[o][j] = (float)qzeros[col + j];
            bif[o][j] = bias[col + j];
        }
    }

#pragma unroll
    for (int mt = 0; mt < 4; mt++)
#pragma unroll
        for (int h = 0; h < 2; h++) {
            const int row = m0 + wm * 64 + mt * 16 + h * 8 + g;
            const float rs = (float)g_rowsum[row];
            float* orow = out + (size_t)row * N_DIM + n0 + wn * 64;
#pragma unroll
            for (int o = 0; o < 8; o++) {
                float2 v;
                v.x = scf[o][0] * (acc[mt][o][h * 2 + 0] - zzf[o][0] * rs) + bif[o][0];
                v.y = scf[o][1] * (acc[mt][o][h * 2 + 1] - zzf[o][1] * rs) + bif[o][1];
                *reinterpret_cast<float2*>(orow + (o >> 1) * 16 + (o & 1) * 8 + tg * 2) = v;
            }
        }
}

// ---------------------------------------------------------------------------
extern "C" void kernel_launch(void* const* d_in, const int* in_sizes, int n_in,
                              void* d_out, int out_size) {
    const float* x       = (const float*)d_in[0];   // [4096, 4096] f32
    const int*   qweight = (const int*)  d_in[1];   // [11008, 2048] i32
    const int*   qzeros  = (const int*)  d_in[2];   // [11008, 1] i32
    const float* scales  = (const float*)d_in[3];   // [11008, 1] f32
    const float* bias    = (const float*)d_in[4];   // [11008] f32
    const float* clampv  = (const float*)d_in[5];   // [1] f32
    float* out = (float*)d_out;                     // [4096, 11008] f32

    cudaFuncSetAttribute(gemm_kernel, cudaFuncAttributeMaxDynamicSharedMemorySize, 3 * STG);

    quantize_kernel<<<M_DIM, 256>>>(x, clampv);
    unpack_kernel<<<N_DIM, 256>>>(qweight);
    gemm_kernel<<<dim3(N_DIM / BN, M_DIM / BM), 256, 3 * STG>>>(qzeros, scales, bias,
                                                                clampv, out);
}